// round 16
// baseline (speedup 1.0000x reference)
#include <cuda_runtime.h>
#include <math.h>

#define Bsz 128
#define Tlen 48
#define Dm 512
#define NBLK 128
#define NTHR 512

// ---------------- global scratch ---------------------------------------------
__device__ float g_w[Bsz*Tlen*64];
__device__ unsigned long long g_code[Bsz*Tlen*2];
__device__ int g_src[Bsz*Tlen];
__device__ float g_read[Bsz*Dm];
__device__ float g_f[Bsz*Dm];
__device__ float g_we[Bsz*Dm];
__device__ float g_ft[Tlen*Bsz*Dm];
__device__ float g_H[(Tlen+1)*Bsz*Dm];
__device__ float g_C[(Tlen+1)*Bsz*Dm];
// k-major weight slabs (built once per launch by stage_wtr; tf32-rounded for mma)
__device__ float g_WTf[16*1024*32];    // [cg][k][n]  Wf   (tf32)
__device__ float g_WTa2[16*1024*32];   // [cg][k][n]  Wa   (tf32)
__device__ float g_WTe[16*512*32];     // [cg][k][n]  We   (tf32)
__device__ float g_WTad[16*512*32];    // [cg][k][n]  Wadd (tf32)
__device__ float g_WTl[16*4*1024*32];  // [cg][gate][k(ih|hh)][n]  (tf32)
// barriers: monotonic counters (graph-replay safe)
__device__ unsigned g_count = 0;
__device__ volatile unsigned g_sense = 0;
__device__ unsigned g_gcnt[8*32];
__device__ volatile unsigned g_gsense[8*32];

__device__ __forceinline__ float sigm(float x) { return 1.0f / (1.0f + expf(-x)); }

// per-warp-group (128-thread) named barrier: ids 1..4
__device__ __forceinline__ void barg(int g) {
    asm volatile("bar.sync %0, 128;" :: "r"(g + 1) : "memory");
}

// tf32 round (rna) -> b32
__device__ __forceinline__ unsigned f2tf(float x) {
    unsigned u; asm("cvt.rna.tf32.f32 %0, %1;" : "=r"(u) : "f"(x)); return u;
}

// m16n8k8 tf32 mma, fp32 accumulate
__device__ __forceinline__ void mma_tf32(float (&d)[4], unsigned a0, unsigned a1,
                                         unsigned a2, unsigned a3,
                                         unsigned b0, unsigned b1) {
    asm volatile(
        "mma.sync.aligned.m16n8k8.row.col.f32.tf32.tf32.f32 "
        "{%0,%1,%2,%3}, {%4,%5,%6,%7}, {%8,%9}, {%0,%1,%2,%3};"
        : "+f"(d[0]), "+f"(d[1]), "+f"(d[2]), "+f"(d[3])
        : "r"(a0), "r"(a1), "r"(a2), "r"(a3), "r"(b0), "r"(b1));
}

// smem layout (floats):
// [0,32768) memS. During lstm phase reused:
//   W bufs 3 x 9216 at [0,27648) (buf i: gate g at i*9216+g*2304), A 2x1280 at [27648,30208)
// AS 4x1280 (A dbl-buf fwe/ea) | WS 4x1184 (W buf0) |
// PART 16x576 (fwe/ea overlay W buf1/buf2 at g*2304, g*2304+1152) | wT | wN | i16
#define OFF_AS   32768
#define OFF_WS   37888
#define OFF_PART 42624
#define OFF_WT   51840
#define OFF_WN   52864
#define OFF_I16  53888
#define SMEM_FLOATS 53904
#define SMEM_BYTES (SMEM_FLOATS * 4)

// ---------------- cp.async helpers --------------------------------------------
__device__ __forceinline__ void cpa16(unsigned dst, const float* src) {
    asm volatile("cp.async.cg.shared.global [%0], [%1], 16;" :: "r"(dst), "l"(src));
}
__device__ __forceinline__ void cpa_commit() {
    asm volatile("cp.async.commit_group;" ::: "memory");
}
__device__ __forceinline__ void cpa_wait1() {
    asm volatile("cp.async.wait_group 1;" ::: "memory");
}
__device__ __forceinline__ void cpa_wait0() {
    asm volatile("cp.async.wait_group 0;" ::: "memory");
}

// ---------------- global grid barrier -----------------------------------------
__device__ __forceinline__ void gsync(unsigned& ls) {
    __syncthreads();
    if (threadIdx.x == 0) {
        unsigned target = ls + 1u;
        __threadfence();
        unsigned a = atomicAdd(&g_count, 1u) + 1u;
        if (a == target * (unsigned)NBLK) g_sense = target;
        while (g_sense != target) { }
        ls = target;
        __threadfence();
    }
    __syncthreads();
}

// ---------------- group barrier: 16 blocks sharing one row-group --------------
__device__ __forceinline__ void gsync_grp(unsigned& ls, int grp32) {
    __syncthreads();
    if (threadIdx.x == 0) {
        unsigned target = ls + 1u;
        __threadfence();
        unsigned a = atomicAdd(&g_gcnt[grp32], 1u) + 1u;
        if (a == target * 16u) g_gsense[grp32] = target;
        while (g_gsense[grp32] != target) { }
        ls = target;
        __threadfence();
    }
    __syncthreads();
}

__device__ __forceinline__ void fma16(float (&acc)[4][4], float4 a, float4 w) {
    acc[0][0]=fmaf(a.x,w.x,acc[0][0]); acc[0][1]=fmaf(a.x,w.y,acc[0][1]);
    acc[0][2]=fmaf(a.x,w.z,acc[0][2]); acc[0][3]=fmaf(a.x,w.w,acc[0][3]);
    acc[1][0]=fmaf(a.y,w.x,acc[1][0]); acc[1][1]=fmaf(a.y,w.y,acc[1][1]);
    acc[1][2]=fmaf(a.y,w.z,acc[1][2]); acc[1][3]=fmaf(a.y,w.w,acc[1][3]);
    acc[2][0]=fmaf(a.z,w.x,acc[2][0]); acc[2][1]=fmaf(a.z,w.y,acc[2][1]);
    acc[2][2]=fmaf(a.z,w.z,acc[2][2]); acc[2][3]=fmaf(a.z,w.w,acc[2][3]);
    acc[3][0]=fmaf(a.w,w.x,acc[3][0]); acc[3][1]=fmaf(a.w,w.y,acc[3][1]);
    acc[3][2]=fmaf(a.w,w.z,acc[3][2]); acc[3][3]=fmaf(a.w,w.w,acc[3][3]);
}

// ---------------- one-time k-major weight transposes (tf32-rounded) -----------
__device__ void stage_wtr(const float* __restrict__ Wf, const float* __restrict__ Wa,
                          const float* __restrict__ We, const float* __restrict__ Wadd,
                          const float* __restrict__ Wih, const float* __restrict__ Whh)
{
    const int gid = blockIdx.x * NTHR + threadIdx.x;
    const int gs = NBLK * NTHR;   // 65536
    for (int d = gid; d < 16*1024*32; d += gs) {
        int cg = d >> 15, n = (d >> 10) & 31, k = d & 1023;
        int dst = (cg << 15) + k * 32 + n;
        g_WTf[dst]  = __uint_as_float(f2tf(Wf[(size_t)(cg * 32 + n) * 1024 + k]));
        g_WTa2[dst] = __uint_as_float(f2tf(Wa[(size_t)(cg * 32 + n) * 1024 + k]));
    }
    for (int d = gid; d < 16*512*32; d += gs) {
        int cg = d >> 14, n = (d >> 9) & 31, k = d & 511;
        int dst = (cg << 14) + k * 32 + n;
        g_WTe[dst]  = __uint_as_float(f2tf(We[(size_t)(cg * 32 + n) * 512 + k]));
        g_WTad[dst] = __uint_as_float(f2tf(Wadd[(size_t)(cg * 32 + n) * 512 + k]));
    }
    for (int d = gid; d < 16*4*1024*32; d += gs) {
        int cg = d >> 17, gate = (d >> 15) & 3, n = (d >> 10) & 31, k = d & 1023;
        int dst = ((cg * 4 + gate) << 15) + k * 32 + n;
        float v = (k < 512)
            ? Wih[(size_t)(gate * 512 + cg * 32 + n) * 512 + k]
            : Whh[(size_t)(gate * 512 + cg * 32 + n) * 512 + (k - 512)];
        g_WTl[dst] = __uint_as_float(f2tf(v));
    }
}

// ---------------- addressing GEMM: g_w[6144,64] = ktab[q] @ Mk^T (fp32) ------
__device__ void stage_addr(float* sm, const float* __restrict__ Mk,
                           const float* __restrict__ ktab, const int* __restrict__ q)
{
    float* As = sm + OFF_AS;      // [32][68]
    float* Ws = sm + OFF_WS;      // [32][36]
    float* part = sm + OFF_PART;  // [4][64][36]
    const int tid = threadIdx.x;
    const int s = tid >> 7, pos = tid & 127, rg = pos >> 3, cg = pos & 7;
    for (int tile = blockIdx.x; tile < 192; tile += NBLK) {
        const int row0 = (tile >> 1) * 64, cc0 = (tile & 1) * 32;
        float acc[4][4] = {};
#pragma unroll 1
        for (int ch = 0; ch < 16; ch++) {
            const int kb = ch * 32;
            {
                int rr = tid >> 3, kq = tid & 7;
                int qi = q[row0 + rr];
                float4 v = *(const float4*)(ktab + (size_t)qi * Dm + kb + kq * 4);
                float* a = As + (kq * 4) * 68 + rr;
                a[0] = v.x; a[68] = v.y; a[136] = v.z; a[204] = v.w;
            }
            if (tid < 256) {
                int n = tid >> 3, kq = tid & 7;
                float4 v = *(const float4*)(Mk + (size_t)(cc0 + n) * Dm + kb + kq * 4);
                float* w = Ws + (kq * 4) * 36 + n;
                w[0] = v.x; w[36] = v.y; w[72] = v.z; w[108] = v.w;
            }
            __syncthreads();
#pragma unroll
            for (int kk = 0; kk < 8; kk++) {
                int k = s * 8 + kk;
                float4 a4 = *(const float4*)(As + k * 68 + rg * 4);
                float4 w4 = *(const float4*)(Ws + k * 36 + cg * 4);
                fma16(acc, a4, w4);
            }
            __syncthreads();
        }
#pragma unroll
        for (int j = 0; j < 4; j++)
            *(float4*)(part + s * 2304 + (rg * 4 + j) * 36 + cg * 4) =
                make_float4(acc[j][0], acc[j][1], acc[j][2], acc[j][3]);
        __syncthreads();
        {
            int rr = tid >> 3, cgx = tid & 7;
            float4 v = make_float4(0.f, 0.f, 0.f, 0.f);
#pragma unroll
            for (int p = 0; p < 4; p++) {
                float4 u = *(const float4*)(part + p * 2304 + rr * 36 + cgx * 4);
                v.x += u.x; v.y += u.y; v.z += u.z; v.w += u.w;
            }
            *(float4*)(g_w + (size_t)(row0 + rr) * 64 + cc0 + cgx * 4) = v;
        }
        __syncthreads();
    }
}

// ---------------- softmax + triangular membership codes ----------------------
__device__ void stage_softmax(float* sm)
{
    unsigned char* ivb = (unsigned char*)(sm + OFF_WT);  // [16][64]
    const int wp = threadIdx.x >> 5, lane = threadIdx.x & 31;
    for (int rr = wp; rr < 48; rr += 16) {
        const int row = blockIdx.x * 48 + rr;
        float v0 = g_w[row * 64 + lane];
        float v1 = g_w[row * 64 + 32 + lane];
        float mx = fmaxf(v0, v1);
        for (int o = 16; o; o >>= 1) mx = fmaxf(mx, __shfl_xor_sync(0xffffffffu, mx, o));
        float e0 = expf(v0 - mx), e1 = expf(v1 - mx);
        float ss = e0 + e1;
        for (int o = 16; o; o >>= 1) ss += __shfl_xor_sync(0xffffffffu, ss, o);
        float inv = 1.0f / ss;
        float w0 = e0 * inv, w1 = e1 * inv;
        g_w[row * 64 + lane] = w0;
        g_w[row * 64 + 32 + lane] = w1;
        auto ivf = [](float w) -> int {
            float m = fmaxf(fminf((w - 0.075f) / (0.088f - 0.075f),
                                  (1.0f - w) / (1.0f - 0.088f)), 0.0f);
            return (m >= 0.6f) ? 2 : ((m >= 0.1f) ? 1 : 0);
        };
        ivb[wp * 64 + lane] = (unsigned char)ivf(w0);
        ivb[wp * 64 + 32 + lane] = (unsigned char)ivf(w1);
        __syncwarp();
        if (lane == 0) {
            unsigned long long c0 = 0ull, c1 = 0ull;
            for (int i = 0; i < 32; i++) {
                c0 |= (unsigned long long)ivb[wp * 64 + i] << (2 * i);
                c1 |= (unsigned long long)ivb[wp * 64 + 32 + i] << (2 * i);
            }
            g_code[row * 2] = c0;
            g_code[row * 2 + 1] = c1;
        }
        __syncwarp();
    }
}

// ---------------- src scan + memS / H0 / C0 / read_0 init --------------------
__device__ void stage_init(float* sm, const float* __restrict__ Mv0,
                           const float* __restrict__ hx0, const float* __restrict__ cx0,
                           int r0, int c0)
{
    float* memS = sm;
    float* wT = sm + OFF_WT;
    const int tid = threadIdx.x;
    if (tid < Tlen) {
        const int b = blockIdx.x, i = tid;
        unsigned long long cc0 = g_code[(b * Tlen + i) * 2];
        unsigned long long cc1 = g_code[(b * Tlen + i) * 2 + 1];
        int sv = i - 1;
        for (int j = i - 1; j >= 0; j--)
            if (g_code[(b * Tlen + j) * 2] == cc0 && g_code[(b * Tlen + j) * 2 + 1] == cc1) { sv = j; break; }
        g_src[b * Tlen + i] = sv;
    }
    for (int i = tid; i < 32768; i += NTHR) {
        int m = (i >> 5) & 63, cc = i & 31;
        memS[i] = Mv0[m * Dm + c0 + cc];
    }
    for (int i = tid; i < 1024; i += NTHR) {
        int bl = i >> 6, m = i & 63;
        wT[i] = g_w[((r0 + bl) * Tlen) * 64 + m];
    }
    __syncthreads();
    const int rr = tid >> 5, cc = tid & 31;
    const int b = r0 + rr, col = c0 + cc;
    g_H[(size_t)b * Dm + col] = hx0[col];
    g_C[(size_t)b * Dm + col] = cx0[col];
    float racc = 0.f;
#pragma unroll 4
    for (int m = 0; m < 64; m++)
        racc = fmaf(wT[rr * 64 + m], memS[(rr * 64 + m) * 32 + cc], racc);
    g_read[(size_t)b * Dm + col] = racc;
}

// ---------------- f / we GEMM: tf32 mma, depth-3 W / depth-2 A pipeline -------
template<int MODE>   // 0: f = tanh(.), X=g_read, tab=ktab ; 1: we = raw, X=g_f, tab=xtab
__device__ void stage_fwe(float* sm, const float* __restrict__ bias,
                          const float* __restrict__ tab, const int* __restrict__ q,
                          const int* __restrict__ r, int t, int r0, int c0)
{
    float* part = sm + OFF_PART;
    int* sQ = (int*)(sm + OFF_I16);
    const int tid = threadIdx.x;
    const int g = tid >> 7, gt = tid & 127;
    const int s = gt >> 5, lane = tid & 31;
    if (tid < 16) {
        int b = r0 + tid;
        int qi = q[b * Tlen + t];
        sQ[tid] = (MODE == 0) ? qi : (qi + 2000 * r[b * Tlen + t]);
    }
    __syncthreads();
    const float* X = (MODE == 0) ? g_read : g_f;
    const float* slab = ((MODE == 0) ? g_WTf : g_WTa2) + ((size_t)(c0 >> 5) << 15);

    const int wk0 = (gt * 2) >> 3, wsg0 = (gt * 2) & 7;
    const int wk1 = (gt * 2 + 1) >> 3, wsg1 = (gt * 2 + 1) & 7;
    float* wb[3];
    wb[0] = sm + OFF_WS + g * 1184;
    wb[1] = part + g * 2304;
    wb[2] = part + g * 2304 + 1152;
    unsigned wbu[3];
#pragma unroll
    for (int i = 0; i < 3; i++) wbu[i] = (unsigned)__cvta_generic_to_shared(wb[i]);
    const unsigned wo0 = (unsigned)(wk0 * 36 + wsg0 * 4) * 4u;
    const unsigned wo1 = (unsigned)(wk1 * 36 + wsg1 * 4) * 4u;
    unsigned* Ab[2];
    Ab[0] = (unsigned*)(sm + OFF_AS) + g * 1280;
    Ab[1] = Ab[0] + 640;
    const int arr = gt >> 3, akq = gt & 7;

    {   // prologue: W0 -> buf0, W1 -> buf1 (separate commit groups)
        int kb = g * 256;
        cpa16(wbu[0] + wo0, slab + (size_t)(kb + wk0) * 32 + wsg0 * 4);
        cpa16(wbu[0] + wo1, slab + (size_t)(kb + wk1) * 32 + wsg1 * 4);
        cpa_commit();
        kb += 32;
        cpa16(wbu[1] + wo0, slab + (size_t)(kb + wk0) * 32 + wsg0 * 4);
        cpa16(wbu[1] + wo1, slab + (size_t)(kb + wk1) * 32 + wsg1 * 4);
        cpa_commit();
    }
    float4 aR;
    {
        int kb = g * 256;
        const float* srcp = (g < 2) ? X + (size_t)(r0 + arr) * Dm + kb + akq * 4
                                    : tab + (size_t)sQ[arr] * Dm + (kb - Dm) + akq * 4;
        aR = *(const float4*)srcp;
    }
    float dacc[4][4] = {};
#pragma unroll 1
    for (int ch = 0; ch < 8; ch++) {
        unsigned* Ag = Ab[ch & 1];
        {   // store A chunk ch (k-major, tf32)
            unsigned* a = Ag + (akq * 4) * 20 + arr;
            a[0] = f2tf(aR.x); a[20] = f2tf(aR.y); a[40] = f2tf(aR.z); a[60] = f2tf(aR.w);
        }
        float4 aN = aR;
        if (ch < 7) {
            int kb = g * 256 + (ch + 1) * 32;
            const float* srcp = (g < 2) ? X + (size_t)(r0 + arr) * Dm + kb + akq * 4
                                        : tab + (size_t)sQ[arr] * Dm + (kb - Dm) + akq * 4;
            aN = *(const float4*)srcp;
            cpa_wait1();
        } else {
            cpa_wait0();
        }
        barg(g);
        if (ch < 6) {   // issue W ch+2 into buf[(ch+2)%3] (safe: all finished compute ch-1)
            int kb = g * 256 + (ch + 2) * 32;
            unsigned wd = wbu[(ch + 2) % 3];
            cpa16(wd + wo0, slab + (size_t)(kb + wk0) * 32 + wsg0 * 4);
            cpa16(wd + wo1, slab + (size_t)(kb + wk1) * 32 + wsg1 * 4);
            cpa_commit();
        }
        const unsigned* Wb = (const unsigned*)wb[ch % 3];
        const int kl = s * 8;
        unsigned a0 = Ag[(kl + (lane & 3)) * 20 + (lane >> 2)];
        unsigned a1 = Ag[(kl + (lane & 3)) * 20 + (lane >> 2) + 8];
        unsigned a2 = Ag[(kl + 4 + (lane & 3)) * 20 + (lane >> 2)];
        unsigned a3 = Ag[(kl + 4 + (lane & 3)) * 20 + (lane >> 2) + 8];
#pragma unroll
        for (int nt = 0; nt < 4; nt++) {
            unsigned b0 = Wb[(kl + (lane & 3)) * 36 + nt * 8 + (lane >> 2)];
            unsigned b1 = Wb[(kl + 4 + (lane & 3)) * 36 + nt * 8 + (lane >> 2)];
            mma_tf32(dacc[nt], a0, a1, a2, a3, b0, b1);
        }
        aR = aN;
    }
    barg(g);   // group done reading wb1/wb2 (part overlay) before partial writes
    const int sid = g * 4 + s;
    {
        const int row = lane >> 2, colb = (lane & 3) * 2;
        float* pb = part + sid * 576;
#pragma unroll
        for (int nt = 0; nt < 4; nt++) {
            pb[row * 36 + nt * 8 + colb]           = dacc[nt][0];
            pb[row * 36 + nt * 8 + colb + 1]       = dacc[nt][1];
            pb[(row + 8) * 36 + nt * 8 + colb]     = dacc[nt][2];
            pb[(row + 8) * 36 + nt * 8 + colb + 1] = dacc[nt][3];
        }
    }
    __syncthreads();
    {
        const int rr = tid >> 5, cc = tid & 31;
        float v = 0.f;
#pragma unroll
        for (int p = 0; p < 16; p++) v += part[p * 576 + rr * 36 + cc];
        v += bias[c0 + cc];
        const int b = r0 + rr;
        if (MODE == 0) {
            v = tanhf(v);
            g_f[(size_t)b * Dm + c0 + cc] = v;
            g_ft[((size_t)t * Bsz + b) * Dm + c0 + cc] = v;
        } else {
            g_we[(size_t)b * Dm + c0 + cc] = v;
        }
    }
}

// ---------------- e/a GEMMs (tf32 mma, depth-3 pipeline) + mem update --------
__device__ void stage_ea(float* sm, const float* __restrict__ be,
                         const float* __restrict__ ba, int t, int r0, int c0)
{
    float* memS = sm;
    float* part = sm + OFF_PART;
    float* wT = sm + OFF_WT;
    float* wN = sm + OFF_WN;
    const int tid = threadIdx.x;
    const int g = tid >> 7, gt = tid & 127;
    const int s = gt >> 5, lane = tid & 31;
    for (int i = tid; i < 1024; i += NTHR) {
        int bl = i >> 6, m = i & 63;
        wT[i] = g_w[((r0 + bl) * Tlen + t) * 64 + m];
        wN[i] = (t + 1 < Tlen) ? g_w[((r0 + bl) * Tlen + t + 1) * 64 + m] : 0.0f;
    }
    __syncthreads();
    const float* slab = ((g < 2) ? g_WTe : g_WTad) + ((size_t)(c0 >> 5) << 14);

    const int wk0 = (gt * 2) >> 3, wsg0 = (gt * 2) & 7;
    const int wk1 = (gt * 2 + 1) >> 3, wsg1 = (gt * 2 + 1) & 7;
    float* wb[3];
    wb[0] = sm + OFF_WS + g * 1184;
    wb[1] = part + g * 2304;
    wb[2] = part + g * 2304 + 1152;
    unsigned wbu[3];
#pragma unroll
    for (int i = 0; i < 3; i++) wbu[i] = (unsigned)__cvta_generic_to_shared(wb[i]);
    const unsigned wo0 = (unsigned)(wk0 * 36 + wsg0 * 4) * 4u;
    const unsigned wo1 = (unsigned)(wk1 * 36 + wsg1 * 4) * 4u;
    unsigned* Ab[2];
    Ab[0] = (unsigned*)(sm + OFF_AS) + g * 1280;
    Ab[1] = Ab[0] + 640;
    const int arr = gt >> 3, akq = gt & 7;
    const int kh = (g & 1) * 256;

    {
        cpa16(wbu[0] + wo0, slab + (size_t)(kh + wk0) * 32 + wsg0 * 4);
        cpa16(wbu[0] + wo1, slab + (size_t)(kh + wk1) * 32 + wsg1 * 4);
        cpa_commit();
        cpa16(wbu[1] + wo0, slab + (size_t)(kh + 32 + wk0) * 32 + wsg0 * 4);
        cpa16(wbu[1] + wo1, slab + (size_t)(kh + 32 + wk1) * 32 + wsg1 * 4);
        cpa_commit();
    }
    float4 aR = *(const float4*)(g_we + (size_t)(r0 + arr) * Dm + kh + akq * 4);
    float dacc[4][4] = {};
#pragma unroll 1
    for (int ch = 0; ch < 8; ch++) {
        unsigned* Ag = Ab[ch & 1];
        {
            unsigned* a = Ag + (akq * 4) * 20 + arr;
            a[0] = f2tf(aR.x); a[20] = f2tf(aR.y); a[40] = f2tf(aR.z); a[60] = f2tf(aR.w);
        }
        float4 aN = aR;
        if (ch < 7) {
            int kb = kh + (ch + 1) * 32;
            aN = *(const float4*)(g_we + (size_t)(r0 + arr) * Dm + kb + akq * 4);
            cpa_wait1();
        } else {
            cpa_wait0();
        }
        barg(g);
        if (ch < 6) {
            int kb = kh + (ch + 2) * 32;
            unsigned wd = wbu[(ch + 2) % 3];
            cpa16(wd + wo0, slab + (size_t)(kb + wk0) * 32 + wsg0 * 4);
            cpa16(wd + wo1, slab + (size_t)(kb + wk1) * 32 + wsg1 * 4);
            cpa_commit();
        }
        const unsigned* Wb = (const unsigned*)wb[ch % 3];
        const int kl = s * 8;
        unsigned a0 = Ag[(kl + (lane & 3)) * 20 + (lane >> 2)];
        unsigned a1 = Ag[(kl + (lane & 3)) * 20 + (lane >> 2) + 8];
        unsigned a2 = Ag[(kl + 4 + (lane & 3)) * 20 + (lane >> 2)];
        unsigned a3 = Ag[(kl + 4 + (lane & 3)) * 20 + (lane >> 2) + 8];
#pragma unroll
        for (int nt = 0; nt < 4; nt++) {
            unsigned b0 = Wb[(kl + (lane & 3)) * 36 + nt * 8 + (lane >> 2)];
            unsigned b1 = Wb[(kl + 4 + (lane & 3)) * 36 + nt * 8 + (lane >> 2)];
            mma_tf32(dacc[nt], a0, a1, a2, a3, b0, b1);
        }
        aR = aN;
    }
    barg(g);
    const int sid = g * 4 + s;
    {
        const int row = lane >> 2, colb = (lane & 3) * 2;
        float* pb = part + sid * 576;
#pragma unroll
        for (int nt = 0; nt < 4; nt++) {
            pb[row * 36 + nt * 8 + colb]           = dacc[nt][0];
            pb[row * 36 + nt * 8 + colb + 1]       = dacc[nt][1];
            pb[(row + 8) * 36 + nt * 8 + colb]     = dacc[nt][2];
            pb[(row + 8) * 36 + nt * 8 + colb + 1] = dacc[nt][3];
        }
    }
    __syncthreads();
    {
        const int rr = tid >> 5, cc = tid & 31;
        float ve = 0.f, va = 0.f;
#pragma unroll
        for (int p = 0; p < 8; p++)  ve += part[p * 576 + rr * 36 + cc];
#pragma unroll
        for (int p = 8; p < 16; p++) va += part[p * 576 + rr * 36 + cc];
        ve = sigm(ve + be[c0 + cc]);
        va = tanhf(va + ba[c0 + cc]);
        float racc = 0.f;
#pragma unroll 4
        for (int m = 0; m < 64; m++) {
            float wt = wT[rr * 64 + m], wn = wN[rr * 64 + m];
            float* p = &memS[(rr * 64 + m) * 32 + cc];
            float v = *p;
            v = v * (1.0f - wt * ve) + wt * va;
            *p = v;
            racc = fmaf(wn, v, racc);
        }
        g_read[(size_t)(r0 + rr) * Dm + c0 + cc] = racc;
    }
}

// ---------------- hop-LSTM step: tf32 mma, depth-3 W / depth-2 A, 16 chunks ---
__device__ void stage_lstm(float* sm, const float* __restrict__ bih,
                           const float* __restrict__ bhh, int t, int r0, int c0)
{
    float* part = sm + OFF_PART;
    int* s16 = (int*)(sm + OFF_I16);
    const int tid = threadIdx.x;
    const int w = tid >> 5, lane = tid & 31;
    const int gate = w >> 2, ks = w & 3;
    const int g = tid >> 7, gt = tid & 127;
    if (tid < 16) s16[tid] = g_src[(r0 + tid) * Tlen + t] + 1;
    __syncthreads();

    const float* slab = g_WTl + ((size_t)((c0 >> 5) * 4 + g) << 15);
    int wk[4], wsg[4]; unsigned wo[4];
#pragma unroll
    for (int h = 0; h < 4; h++) {
        int i = gt * 4 + h;
        wk[h] = i >> 3; wsg[h] = i & 7;
        wo[h] = (unsigned)(wk[h] * 36 + wsg[h] * 4) * 4u;
    }
    // W buffers: 3 x (4 gates x 2304) in memS region
    unsigned wbu[3];
#pragma unroll
    for (int i = 0; i < 3; i++)
        wbu[i] = (unsigned)__cvta_generic_to_shared(sm + i * 9216 + g * 2304);
    unsigned* aL[2];
    aL[0] = (unsigned*)(sm + 27648);
    aL[1] = aL[0] + 1280;

    const int arow = tid & 15, aseg = tid >> 4;
    const float* aF = g_ft + ((size_t)t * Bsz + r0 + arow) * Dm + aseg * 4;
    const float* aH = g_H + ((size_t)s16[arow] * Bsz + r0 + arow) * Dm + aseg * 4;

    {   // prologue: W0 -> buf0, W1 -> buf1
#pragma unroll
        for (int h = 0; h < 4; h++)
            cpa16(wbu[0] + wo[h], slab + (size_t)wk[h] * 32 + wsg[h] * 4);
        cpa_commit();
#pragma unroll
        for (int h = 0; h < 4; h++)
            cpa16(wbu[1] + wo[h], slab + (size_t)(64 + wk[h]) * 32 + wsg[h] * 4);
        cpa_commit();
    }
    float4 aR = make_float4(0.f, 0.f, 0.f, 0.f);
    if (tid < 256) aR = *(const float4*)aF;

    float dacc[4][4] = {};
#pragma unroll 1
    for (int ch = 0; ch < 16; ch++) {
        unsigned* aLu = aL[ch & 1];
        if (tid < 256) {
            unsigned* a = aLu + (aseg * 4) * 20 + arow;
            a[0]  = f2tf(aR.x); a[20] = f2tf(aR.y);
            a[40] = f2tf(aR.z); a[60] = f2tf(aR.w);
        }
        float4 aN = aR;
        if (ch < 15) {
            int kb = (ch + 1) * 64;
            if (tid < 256) {
                const float* basep = (kb < Dm) ? aF + kb : aH + (kb - Dm);
                aN = *(const float4*)basep;
            }
            cpa_wait1();
        } else {
            cpa_wait0();
        }
        __syncthreads();
        if (ch < 14) {
            int kb = (ch + 2) * 64;
            unsigned wd = wbu[(ch + 2) % 3];
#pragma unroll
            for (int h = 0; h < 4; h++)
                cpa16(wd + wo[h], slab + (size_t)(kb + wk[h]) * 32 + wsg[h] * 4);
            cpa_commit();
        }
        const unsigned* Wg = (const unsigned*)(sm + (ch % 3) * 9216) + gate * 2304;
#pragma unroll
        for (int kt = 0; kt < 2; kt++) {
            const int kl = ks * 16 + kt * 8;
            unsigned a0 = aLu[(kl + (lane & 3)) * 20 + (lane >> 2)];
            unsigned a1 = aLu[(kl + (lane & 3)) * 20 + (lane >> 2) + 8];
            unsigned a2 = aLu[(kl + 4 + (lane & 3)) * 20 + (lane >> 2)];
            unsigned a3 = aLu[(kl + 4 + (lane & 3)) * 20 + (lane >> 2) + 8];
#pragma unroll
            for (int nt = 0; nt < 4; nt++) {
                unsigned b0 = Wg[(kl + (lane & 3)) * 36 + nt * 8 + (lane >> 2)];
                unsigned b1 = Wg[(kl + 4 + (lane & 3)) * 36 + nt * 8 + (lane >> 2)];
                mma_tf32(dacc[nt], a0, a1, a2, a3, b0, b1);
            }
        }
        aR = aN;
    }
    const int sid = gate * 4 + ks;
    {
        const int row = lane >> 2, colb = (lane & 3) * 2;
#pragma unroll
        for (int nt = 0; nt < 4; nt++) {
            float* pb = part + sid * 576;
            pb[row * 36 + nt * 8 + colb]           = dacc[nt][0];
            pb[row * 36 + nt * 8 + colb + 1]       = dacc[nt][1];
            pb[(row + 8) * 36 + nt * 8 + colb]     = dacc[nt][2];
            pb[(row + 8) * 36 + nt * 8 + colb + 1] = dacc[nt][3];
        }
    }
    __syncthreads();
    {
        const int rr = tid >> 5, cc = tid & 31;
        float gi = 0.f, gf = 0.f, gg = 0.f, go = 0.f;
#pragma unroll
        for (int p = 0; p < 4; p++)   gi += part[p * 576 + rr * 36 + cc];
#pragma unroll
        for (int p = 4; p < 8; p++)   gf += part[p * 576 + rr * 36 + cc];
#pragma unroll
        for (int p = 8; p < 12; p++)  gg += part[p * 576 + rr * 36 + cc];
#pragma unroll
        for (int p = 12; p < 16; p++) go += part[p * 576 + rr * 36 + cc];
        const int b = r0 + rr, col = c0 + cc;
        gi += bih[col] + bhh[col];
        gf += bih[512 + col] + bhh[512 + col];
        gg += bih[1024 + col] + bhh[1024 + col];
        go += bih[1536 + col] + bhh[1536 + col];
        float cin = g_C[((size_t)s16[rr] * Bsz + b) * Dm + col];
        float cn = sigm(gf) * cin + sigm(gi) * tanhf(gg);
        float hn = sigm(go) * tanhf(cn);
        g_C[((size_t)(t + 1) * Bsz + b) * Dm + col] = cn;
        g_H[((size_t)(t + 1) * Bsz + b) * Dm + col] = hn;
    }
}

// ---------------- prediction head --------------------------------------------
__device__ void stage_head(const float* __restrict__ Wp, const float* __restrict__ bp,
                           float* __restrict__ out)
{
    const int wp = threadIdx.x >> 5, lane = threadIdx.x & 31;
    for (int bt = blockIdx.x * 16 + wp; bt < Bsz * Tlen; bt += NBLK * 16) {
        const int b = bt / Tlen, t = bt % Tlen;
        const float* h = &g_H[((size_t)(t + 1) * Bsz + b) * Dm];
        float s = 0.f;
        for (int i = lane; i < Dm; i += 32) s = fmaf(h[i], Wp[i], s);
        for (int o = 16; o; o >>= 1) s += __shfl_xor_sync(0xffffffffu, s, o);
        if (lane == 0) out[bt] = sigm(s + bp[0]);
    }
}

// ---------------- the single persistent kernel -------------------------------
__global__ void __launch_bounds__(NTHR, 1) k_persist(
    const int* __restrict__ q, const int* __restrict__ r,
    const float* __restrict__ Mk, const float* __restrict__ Mv0,
    const float* __restrict__ ktab, const float* __restrict__ xtab,
    const float* __restrict__ We, const float* __restrict__ be,
    const float* __restrict__ Wadd, const float* __restrict__ badd,
    const float* __restrict__ Wa, const float* __restrict__ ba,
    const float* __restrict__ Wf, const float* __restrict__ bf,
    const float* __restrict__ Wih, const float* __restrict__ Whh,
    const float* __restrict__ bih, const float* __restrict__ bhh,
    const float* __restrict__ hx0, const float* __restrict__ cx0,
    const float* __restrict__ Wp, const float* __restrict__ bp,
    float* __restrict__ out)
{
    extern __shared__ float sm[];
    const int grp = blockIdx.x & 7;
    const int grp32 = grp * 32;
    unsigned ls = 0, lsr = 0;
    if (threadIdx.x == 0) { ls = g_sense; lsr = g_gsense[grp32]; }
    const int r0 = grp * 16;
    const int c0 = (blockIdx.x >> 3) * 32;

    stage_wtr(Wf, Wa, We, Wadd, Wih, Whh);
    stage_addr(sm, Mk, ktab, q);                          gsync(ls);
    stage_softmax(sm);                                    gsync(ls);
    stage_init(sm, Mv0, hx0, cx0, r0, c0);                gsync(ls);

    for (int t = 0; t < Tlen; t++) {
        stage_fwe<0>(sm, bf, ktab, q, r, t, r0, c0);      gsync_grp(lsr, grp32);
        stage_fwe<1>(sm, ba, xtab, q, r, t, r0, c0);      gsync_grp(lsr, grp32);
        stage_ea(sm, be, badd, t, r0, c0);                gsync_grp(lsr, grp32);
    }
    for (int t = 0; t < Tlen; t++) {
        stage_lstm(sm, bih, bhh, t, r0, c0);              gsync_grp(lsr, grp32);
    }
    gsync(ls);                                            // head reads all rows
    stage_head(Wp, bp, out);
}

// ----------------------------------------------------------------------------
extern "C" void kernel_launch(void* const* d_in, const int* in_sizes, int n_in,
                              void* d_out, int out_size)
{
    const int*   q    = (const int*)d_in[0];
    const int*   r    = (const int*)d_in[1];
    const float* Mk   = (const float*)d_in[2];
    const float* Mv0  = (const float*)d_in[3];
    const float* ktab = (const float*)d_in[4];
    const float* xtab = (const float*)d_in[5];
    const float* We   = (const float*)d_in[6];
    const float* be   = (const float*)d_in[7];
    const float* Wadd = (const float*)d_in[8];
    const float* badd = (const float*)d_in[9];
    const float* Wa   = (const float*)d_in[10];
    const float* ba   = (const float*)d_in[11];
    const float* Wf   = (const float*)d_in[12];
    const float* bf   = (const float*)d_in[13];
    const float* Wih  = (const float*)d_in[14];
    const float* Whh  = (const float*)d_in[15];
    const float* bih  = (const float*)d_in[16];
    const float* bhh  = (const float*)d_in[17];
    const float* hx0  = (const float*)d_in[18];
    const float* cx0  = (const float*)d_in[19];
    const float* Wp   = (const float*)d_in[20];
    const float* bp   = (const float*)d_in[21];
    float* out = (float*)d_out;

    static bool attr_set = false;
    if (!attr_set) {
        cudaFuncSetAttribute(k_persist, cudaFuncAttributeMaxDynamicSharedMemorySize, SMEM_BYTES);
        attr_set = true;
    }
    k_persist<<<NBLK, NTHR, SMEM_BYTES>>>(q, r, Mk, Mv0, ktab, xtab, We, be, Wadd, badd,
                                          Wa, ba, Wf, bf, Wih, Whh, bih, bhh,
                                          hx0, cx0, Wp, bp, out);
}

// round 17
// speedup vs baseline: 1.2181x; 1.2181x over previous
#include <cuda_runtime.h>
#include <math.h>

#define Bsz 128
#define Tlen 48
#define Dm 512
#define NBLK 128
#define NTHR 512

// ---------------- global scratch ---------------------------------------------
__device__ float g_w[Bsz*Tlen*64];
__device__ unsigned long long g_code[Bsz*Tlen*2];
__device__ int g_src[Bsz*Tlen];
__device__ float g_read[Bsz*Dm];
__device__ float g_f[Bsz*Dm];
__device__ float g_we[Bsz*Dm];
__device__ float g_ft[Tlen*Bsz*Dm];
__device__ float g_H[(Tlen+1)*Bsz*Dm];
__device__ float g_C[(Tlen+1)*Bsz*Dm];
// k-major weight slabs (built once per launch by stage_wtr; tf32-rounded for mma)
__device__ float g_WTf[16*1024*32];    // [cg][k][n]  Wf   (tf32)
__device__ float g_WTa2[16*1024*32];   // [cg][k][n]  Wa   (tf32)
__device__ float g_WTe[16*512*32];     // [cg][k][n]  We   (tf32)
__device__ float g_WTad[16*512*32];    // [cg][k][n]  Wadd (tf32)
__device__ float g_WTl[16*4*1024*32];  // [cg][gate][k(ih|hh)][n]  (tf32)
// barriers: monotonic counters (graph-replay safe)
__device__ unsigned g_count = 0;
__device__ volatile unsigned g_sense = 0;
__device__ unsigned g_gcnt[8*32];
__device__ volatile unsigned g_gsense[8*32];

__device__ __forceinline__ float sigm(float x) { return 1.0f / (1.0f + expf(-x)); }

// per-warp-group (128-thread) named barrier: ids 1..4
__device__ __forceinline__ void barg(int g) {
    asm volatile("bar.sync %0, 128;" :: "r"(g + 1) : "memory");
}

// tf32 round (rna) -> b32
__device__ __forceinline__ unsigned f2tf(float x) {
    unsigned u; asm("cvt.rna.tf32.f32 %0, %1;" : "=r"(u) : "f"(x)); return u;
}

// m16n8k8 tf32 mma, fp32 accumulate
__device__ __forceinline__ void mma_tf32(float (&d)[4], unsigned a0, unsigned a1,
                                         unsigned a2, unsigned a3,
                                         unsigned b0, unsigned b1) {
    asm volatile(
        "mma.sync.aligned.m16n8k8.row.col.f32.tf32.tf32.f32 "
        "{%0,%1,%2,%3}, {%4,%5,%6,%7}, {%8,%9}, {%0,%1,%2,%3};"
        : "+f"(d[0]), "+f"(d[1]), "+f"(d[2]), "+f"(d[3])
        : "r"(a0), "r"(a1), "r"(a2), "r"(a3), "r"(b0), "r"(b1));
}

// smem layout (floats):
// [0,32768) memS. During lstm phase reused:
//   W bufs 3 x 9216 at [0,27648) (buf i: gate g at i*9216+g*2304), A 2x1280 at [27648,30208)
// AS 4x1280 (A dbl-buf fwe/ea) | WS 4x1184 (W buf0) |
// PART 16x576 (fwe/ea overlay W buf1/buf2 at g*2304, g*2304+1152) | wT | wN | i16
#define OFF_AS   32768
#define OFF_WS   37888
#define OFF_PART 42624
#define OFF_WT   51840
#define OFF_WN   52864
#define OFF_I16  53888
#define SMEM_FLOATS 53904
#define SMEM_BYTES (SMEM_FLOATS * 4)

// ---------------- cp.async helpers --------------------------------------------
__device__ __forceinline__ void cpa16(unsigned dst, const float* src) {
    asm volatile("cp.async.cg.shared.global [%0], [%1], 16;" :: "r"(dst), "l"(src));
}
__device__ __forceinline__ void cpa_commit() {
    asm volatile("cp.async.commit_group;" ::: "memory");
}
__device__ __forceinline__ void cpa_wait1() {
    asm volatile("cp.async.wait_group 1;" ::: "memory");
}
__device__ __forceinline__ void cpa_wait0() {
    asm volatile("cp.async.wait_group 0;" ::: "memory");
}

// ---------------- global grid barrier -----------------------------------------
__device__ __forceinline__ void gsync(unsigned& ls) {
    __syncthreads();
    if (threadIdx.x == 0) {
        unsigned target = ls + 1u;
        __threadfence();
        unsigned a = atomicAdd(&g_count, 1u) + 1u;
        if (a == target * (unsigned)NBLK) g_sense = target;
        while (g_sense != target) { }
        ls = target;
        __threadfence();
    }
    __syncthreads();
}

// ---------------- group barrier: 16 blocks sharing one row-group --------------
__device__ __forceinline__ void gsync_grp(unsigned& ls, int grp32) {
    __syncthreads();
    if (threadIdx.x == 0) {
        unsigned target = ls + 1u;
        __threadfence();
        unsigned a = atomicAdd(&g_gcnt[grp32], 1u) + 1u;
        if (a == target * 16u) g_gsense[grp32] = target;
        while (g_gsense[grp32] != target) { }
        ls = target;
        __threadfence();
    }
    __syncthreads();
}

__device__ __forceinline__ void fma16(float (&acc)[4][4], float4 a, float4 w) {
    acc[0][0]=fmaf(a.x,w.x,acc[0][0]); acc[0][1]=fmaf(a.x,w.y,acc[0][1]);
    acc[0][2]=fmaf(a.x,w.z,acc[0][2]); acc[0][3]=fmaf(a.x,w.w,acc[0][3]);
    acc[1][0]=fmaf(a.y,w.x,acc[1][0]); acc[1][1]=fmaf(a.y,w.y,acc[1][1]);
    acc[1][2]=fmaf(a.y,w.z,acc[1][2]); acc[1][3]=fmaf(a.y,w.w,acc[1][3]);
    acc[2][0]=fmaf(a.z,w.x,acc[2][0]); acc[2][1]=fmaf(a.z,w.y,acc[2][1]);
    acc[2][2]=fmaf(a.z,w.z,acc[2][2]); acc[2][3]=fmaf(a.z,w.w,acc[2][3]);
    acc[3][0]=fmaf(a.w,w.x,acc[3][0]); acc[3][1]=fmaf(a.w,w.y,acc[3][1]);
    acc[3][2]=fmaf(a.w,w.z,acc[3][2]); acc[3][3]=fmaf(a.w,w.w,acc[3][3]);
}

// ---------------- one-time k-major weight transposes (tf32-rounded) -----------
__device__ void stage_wtr(const float* __restrict__ Wf, const float* __restrict__ Wa,
                          const float* __restrict__ We, const float* __restrict__ Wadd,
                          const float* __restrict__ Wih, const float* __restrict__ Whh)
{
    const int gid = blockIdx.x * NTHR + threadIdx.x;
    const int gs = NBLK * NTHR;   // 65536
    for (int d = gid; d < 16*1024*32; d += gs) {
        int cg = d >> 15, n = (d >> 10) & 31, k = d & 1023;
        int dst = (cg << 15) + k * 32 + n;
        g_WTf[dst]  = __uint_as_float(f2tf(Wf[(size_t)(cg * 32 + n) * 1024 + k]));
        g_WTa2[dst] = __uint_as_float(f2tf(Wa[(size_t)(cg * 32 + n) * 1024 + k]));
    }
    for (int d = gid; d < 16*512*32; d += gs) {
        int cg = d >> 14, n = (d >> 9) & 31, k = d & 511;
        int dst = (cg << 14) + k * 32 + n;
        g_WTe[dst]  = __uint_as_float(f2tf(We[(size_t)(cg * 32 + n) * 512 + k]));
        g_WTad[dst] = __uint_as_float(f2tf(Wadd[(size_t)(cg * 32 + n) * 512 + k]));
    }
    for (int d = gid; d < 16*4*1024*32; d += gs) {
        int cg = d >> 17, gate = (d >> 15) & 3, n = (d >> 10) & 31, k = d & 1023;
        int dst = ((cg * 4 + gate) << 15) + k * 32 + n;
        float v = (k < 512)
            ? Wih[(size_t)(gate * 512 + cg * 32 + n) * 512 + k]
            : Whh[(size_t)(gate * 512 + cg * 32 + n) * 512 + (k - 512)];
        g_WTl[dst] = __uint_as_float(f2tf(v));
    }
}

// ---------------- addressing GEMM: g_w[6144,64] = ktab[q] @ Mk^T (fp32) ------
__device__ void stage_addr(float* sm, const float* __restrict__ Mk,
                           const float* __restrict__ ktab, const int* __restrict__ q)
{
    float* As = sm + OFF_AS;      // [32][68]
    float* Ws = sm + OFF_WS;      // [32][36]
    float* part = sm + OFF_PART;  // [4][64][36]
    const int tid = threadIdx.x;
    const int s = tid >> 7, pos = tid & 127, rg = pos >> 3, cg = pos & 7;
    for (int tile = blockIdx.x; tile < 192; tile += NBLK) {
        const int row0 = (tile >> 1) * 64, cc0 = (tile & 1) * 32;
        float acc[4][4] = {};
#pragma unroll 1
        for (int ch = 0; ch < 16; ch++) {
            const int kb = ch * 32;
            {
                int rr = tid >> 3, kq = tid & 7;
                int qi = q[row0 + rr];
                float4 v = *(const float4*)(ktab + (size_t)qi * Dm + kb + kq * 4);
                float* a = As + (kq * 4) * 68 + rr;
                a[0] = v.x; a[68] = v.y; a[136] = v.z; a[204] = v.w;
            }
            if (tid < 256) {
                int n = tid >> 3, kq = tid & 7;
                float4 v = *(const float4*)(Mk + (size_t)(cc0 + n) * Dm + kb + kq * 4);
                float* w = Ws + (kq * 4) * 36 + n;
                w[0] = v.x; w[36] = v.y; w[72] = v.z; w[108] = v.w;
            }
            __syncthreads();
#pragma unroll
            for (int kk = 0; kk < 8; kk++) {
                int k = s * 8 + kk;
                float4 a4 = *(const float4*)(As + k * 68 + rg * 4);
                float4 w4 = *(const float4*)(Ws + k * 36 + cg * 4);
                fma16(acc, a4, w4);
            }
            __syncthreads();
        }
#pragma unroll
        for (int j = 0; j < 4; j++)
            *(float4*)(part + s * 2304 + (rg * 4 + j) * 36 + cg * 4) =
                make_float4(acc[j][0], acc[j][1], acc[j][2], acc[j][3]);
        __syncthreads();
        {
            int rr = tid >> 3, cgx = tid & 7;
            float4 v = make_float4(0.f, 0.f, 0.f, 0.f);
#pragma unroll
            for (int p = 0; p < 4; p++) {
                float4 u = *(const float4*)(part + p * 2304 + rr * 36 + cgx * 4);
                v.x += u.x; v.y += u.y; v.z += u.z; v.w += u.w;
            }
            *(float4*)(g_w + (size_t)(row0 + rr) * 64 + cc0 + cgx * 4) = v;
        }
        __syncthreads();
    }
}

// ---------------- softmax + triangular membership codes ----------------------
__device__ void stage_softmax(float* sm)
{
    unsigned char* ivb = (unsigned char*)(sm + OFF_WT);  // [16][64]
    const int wp = threadIdx.x >> 5, lane = threadIdx.x & 31;
    for (int rr = wp; rr < 48; rr += 16) {
        const int row = blockIdx.x * 48 + rr;
        float v0 = g_w[row * 64 + lane];
        float v1 = g_w[row * 64 + 32 + lane];
        float mx = fmaxf(v0, v1);
        for (int o = 16; o; o >>= 1) mx = fmaxf(mx, __shfl_xor_sync(0xffffffffu, mx, o));
        float e0 = expf(v0 - mx), e1 = expf(v1 - mx);
        float ss = e0 + e1;
        for (int o = 16; o; o >>= 1) ss += __shfl_xor_sync(0xffffffffu, ss, o);
        float inv = 1.0f / ss;
        float w0 = e0 * inv, w1 = e1 * inv;
        g_w[row * 64 + lane] = w0;
        g_w[row * 64 + 32 + lane] = w1;
        auto ivf = [](float w) -> int {
            float m = fmaxf(fminf((w - 0.075f) / (0.088f - 0.075f),
                                  (1.0f - w) / (1.0f - 0.088f)), 0.0f);
            return (m >= 0.6f) ? 2 : ((m >= 0.1f) ? 1 : 0);
        };
        ivb[wp * 64 + lane] = (unsigned char)ivf(w0);
        ivb[wp * 64 + 32 + lane] = (unsigned char)ivf(w1);
        __syncwarp();
        if (lane == 0) {
            unsigned long long c0 = 0ull, c1 = 0ull;
            for (int i = 0; i < 32; i++) {
                c0 |= (unsigned long long)ivb[wp * 64 + i] << (2 * i);
                c1 |= (unsigned long long)ivb[wp * 64 + 32 + i] << (2 * i);
            }
            g_code[row * 2] = c0;
            g_code[row * 2 + 1] = c1;
        }
        __syncwarp();
    }
}

// ---------------- src scan + memS / H0 / C0 / read_0 init --------------------
__device__ void stage_init(float* sm, const float* __restrict__ Mv0,
                           const float* __restrict__ hx0, const float* __restrict__ cx0,
                           int r0, int c0)
{
    float* memS = sm;
    float* wT = sm + OFF_WT;
    const int tid = threadIdx.x;
    if (tid < Tlen) {
        const int b = blockIdx.x, i = tid;
        unsigned long long cc0 = g_code[(b * Tlen + i) * 2];
        unsigned long long cc1 = g_code[(b * Tlen + i) * 2 + 1];
        int sv = i - 1;
        for (int j = i - 1; j >= 0; j--)
            if (g_code[(b * Tlen + j) * 2] == cc0 && g_code[(b * Tlen + j) * 2 + 1] == cc1) { sv = j; break; }
        g_src[b * Tlen + i] = sv;
    }
    for (int i = tid; i < 32768; i += NTHR) {
        int m = (i >> 5) & 63, cc = i & 31;
        memS[i] = Mv0[m * Dm + c0 + cc];
    }
    for (int i = tid; i < 1024; i += NTHR) {
        int bl = i >> 6, m = i & 63;
        wT[i] = g_w[((r0 + bl) * Tlen) * 64 + m];
    }
    __syncthreads();
    const int rr = tid >> 5, cc = tid & 31;
    const int b = r0 + rr, col = c0 + cc;
    g_H[(size_t)b * Dm + col] = hx0[col];
    g_C[(size_t)b * Dm + col] = cx0[col];
    float racc = 0.f;
#pragma unroll 4
    for (int m = 0; m < 64; m++)
        racc = fmaf(wT[rr * 64 + m], memS[(rr * 64 + m) * 32 + cc], racc);
    g_read[(size_t)b * Dm + col] = racc;
}

// ---------------- f / we GEMM: tf32 mma, depth-3 W / depth-2 A, FULL UNROLL ---
template<int MODE>   // 0: f = tanh(.), X=g_read, tab=ktab ; 1: we = raw, X=g_f, tab=xtab
__device__ void stage_fwe(float* sm, const float* __restrict__ bias,
                          const float* __restrict__ tab, const int* __restrict__ q,
                          const int* __restrict__ r, int t, int r0, int c0)
{
    float* part = sm + OFF_PART;
    int* sQ = (int*)(sm + OFF_I16);
    const int tid = threadIdx.x;
    const int g = tid >> 7, gt = tid & 127;
    const int s = gt >> 5, lane = tid & 31;
    if (tid < 16) {
        int b = r0 + tid;
        int qi = q[b * Tlen + t];
        sQ[tid] = (MODE == 0) ? qi : (qi + 2000 * r[b * Tlen + t]);
    }
    __syncthreads();
    const float* X = (MODE == 0) ? g_read : g_f;
    const float* slab = ((MODE == 0) ? g_WTf : g_WTa2) + ((size_t)(c0 >> 5) << 15);

    const int wk0 = (gt * 2) >> 3, wsg0 = (gt * 2) & 7;
    const int wk1 = (gt * 2 + 1) >> 3, wsg1 = (gt * 2 + 1) & 7;
    float* wb[3];
    wb[0] = sm + OFF_WS + g * 1184;
    wb[1] = part + g * 2304;
    wb[2] = part + g * 2304 + 1152;
    unsigned wbu[3];
#pragma unroll
    for (int i = 0; i < 3; i++) wbu[i] = (unsigned)__cvta_generic_to_shared(wb[i]);
    const unsigned wo0 = (unsigned)(wk0 * 36 + wsg0 * 4) * 4u;
    const unsigned wo1 = (unsigned)(wk1 * 36 + wsg1 * 4) * 4u;
    unsigned* Ab[2];
    Ab[0] = (unsigned*)(sm + OFF_AS) + g * 1280;
    Ab[1] = Ab[0] + 640;
    const int arr = gt >> 3, akq = gt & 7;

    {   // prologue: W0 -> buf0, W1 -> buf1 (separate commit groups)
        int kb = g * 256;
        cpa16(wbu[0] + wo0, slab + (size_t)(kb + wk0) * 32 + wsg0 * 4);
        cpa16(wbu[0] + wo1, slab + (size_t)(kb + wk1) * 32 + wsg1 * 4);
        cpa_commit();
        kb += 32;
        cpa16(wbu[1] + wo0, slab + (size_t)(kb + wk0) * 32 + wsg0 * 4);
        cpa16(wbu[1] + wo1, slab + (size_t)(kb + wk1) * 32 + wsg1 * 4);
        cpa_commit();
    }
    float4 aR;
    {
        int kb = g * 256;
        const float* srcp = (g < 2) ? X + (size_t)(r0 + arr) * Dm + kb + akq * 4
                                    : tab + (size_t)sQ[arr] * Dm + (kb - Dm) + akq * 4;
        aR = *(const float4*)srcp;
    }
    float dacc[4][4] = {};
#pragma unroll
    for (int ch = 0; ch < 8; ch++) {    // FULL UNROLL: buffer indices constant
        unsigned* Ag = Ab[ch & 1];
        {
            unsigned* a = Ag + (akq * 4) * 20 + arr;
            a[0] = f2tf(aR.x); a[20] = f2tf(aR.y); a[40] = f2tf(aR.z); a[60] = f2tf(aR.w);
        }
        float4 aN = aR;
        if (ch < 7) {
            int kb = g * 256 + (ch + 1) * 32;
            const float* srcp = (g < 2) ? X + (size_t)(r0 + arr) * Dm + kb + akq * 4
                                        : tab + (size_t)sQ[arr] * Dm + (kb - Dm) + akq * 4;
            aN = *(const float4*)srcp;
            cpa_wait1();
        } else {
            cpa_wait0();
        }
        barg(g);
        if (ch < 6) {
            int kb = g * 256 + (ch + 2) * 32;
            unsigned wd = wbu[(ch + 2) % 3];
            cpa16(wd + wo0, slab + (size_t)(kb + wk0) * 32 + wsg0 * 4);
            cpa16(wd + wo1, slab + (size_t)(kb + wk1) * 32 + wsg1 * 4);
            cpa_commit();
        }
        const unsigned* Wb = (const unsigned*)wb[ch % 3];
        const int kl = s * 8;
        unsigned a0 = Ag[(kl + (lane & 3)) * 20 + (lane >> 2)];
        unsigned a1 = Ag[(kl + (lane & 3)) * 20 + (lane >> 2) + 8];
        unsigned a2 = Ag[(kl + 4 + (lane & 3)) * 20 + (lane >> 2)];
        unsigned a3 = Ag[(kl + 4 + (lane & 3)) * 20 + (lane >> 2) + 8];
#pragma unroll
        for (int nt = 0; nt < 4; nt++) {
            unsigned b0 = Wb[(kl + (lane & 3)) * 36 + nt * 8 + (lane >> 2)];
            unsigned b1 = Wb[(kl + 4 + (lane & 3)) * 36 + nt * 8 + (lane >> 2)];
            mma_tf32(dacc[nt], a0, a1, a2, a3, b0, b1);
        }
        aR = aN;
    }
    barg(g);   // group done reading wb1/wb2 (part overlay) before partial writes
    const int sid = g * 4 + s;
    {
        const int row = lane >> 2, colb = (lane & 3) * 2;
        float* pb = part + sid * 576;
#pragma unroll
        for (int nt = 0; nt < 4; nt++) {
            pb[row * 36 + nt * 8 + colb]           = dacc[nt][0];
            pb[row * 36 + nt * 8 + colb + 1]       = dacc[nt][1];
            pb[(row + 8) * 36 + nt * 8 + colb]     = dacc[nt][2];
            pb[(row + 8) * 36 + nt * 8 + colb + 1] = dacc[nt][3];
        }
    }
    __syncthreads();
    {
        const int rr = tid >> 5, cc = tid & 31;
        float v = 0.f;
#pragma unroll
        for (int p = 0; p < 16; p++) v += part[p * 576 + rr * 36 + cc];
        v += bias[c0 + cc];
        const int b = r0 + rr;
        if (MODE == 0) {
            v = tanhf(v);
            g_f[(size_t)b * Dm + c0 + cc] = v;
            g_ft[((size_t)t * Bsz + b) * Dm + c0 + cc] = v;
        } else {
            g_we[(size_t)b * Dm + c0 + cc] = v;
        }
    }
}

// ---------------- e/a GEMMs (tf32 mma, depth-3, FULL UNROLL) + mem update ----
__device__ void stage_ea(float* sm, const float* __restrict__ be,
                         const float* __restrict__ ba, int t, int r0, int c0)
{
    float* memS = sm;
    float* part = sm + OFF_PART;
    float* wT = sm + OFF_WT;
    float* wN = sm + OFF_WN;
    const int tid = threadIdx.x;
    const int g = tid >> 7, gt = tid & 127;
    const int s = gt >> 5, lane = tid & 31;
    for (int i = tid; i < 1024; i += NTHR) {
        int bl = i >> 6, m = i & 63;
        wT[i] = g_w[((r0 + bl) * Tlen + t) * 64 + m];
        wN[i] = (t + 1 < Tlen) ? g_w[((r0 + bl) * Tlen + t + 1) * 64 + m] : 0.0f;
    }
    __syncthreads();
    const float* slab = ((g < 2) ? g_WTe : g_WTad) + ((size_t)(c0 >> 5) << 14);

    const int wk0 = (gt * 2) >> 3, wsg0 = (gt * 2) & 7;
    const int wk1 = (gt * 2 + 1) >> 3, wsg1 = (gt * 2 + 1) & 7;
    float* wb[3];
    wb[0] = sm + OFF_WS + g * 1184;
    wb[1] = part + g * 2304;
    wb[2] = part + g * 2304 + 1152;
    unsigned wbu[3];
#pragma unroll
    for (int i = 0; i < 3; i++) wbu[i] = (unsigned)__cvta_generic_to_shared(wb[i]);
    const unsigned wo0 = (unsigned)(wk0 * 36 + wsg0 * 4) * 4u;
    const unsigned wo1 = (unsigned)(wk1 * 36 + wsg1 * 4) * 4u;
    unsigned* Ab[2];
    Ab[0] = (unsigned*)(sm + OFF_AS) + g * 1280;
    Ab[1] = Ab[0] + 640;
    const int arr = gt >> 3, akq = gt & 7;
    const int kh = (g & 1) * 256;

    {
        cpa16(wbu[0] + wo0, slab + (size_t)(kh + wk0) * 32 + wsg0 * 4);
        cpa16(wbu[0] + wo1, slab + (size_t)(kh + wk1) * 32 + wsg1 * 4);
        cpa_commit();
        cpa16(wbu[1] + wo0, slab + (size_t)(kh + 32 + wk0) * 32 + wsg0 * 4);
        cpa16(wbu[1] + wo1, slab + (size_t)(kh + 32 + wk1) * 32 + wsg1 * 4);
        cpa_commit();
    }
    float4 aR = *(const float4*)(g_we + (size_t)(r0 + arr) * Dm + kh + akq * 4);
    float dacc[4][4] = {};
#pragma unroll
    for (int ch = 0; ch < 8; ch++) {    // FULL UNROLL
        unsigned* Ag = Ab[ch & 1];
        {
            unsigned* a = Ag + (akq * 4) * 20 + arr;
            a[0] = f2tf(aR.x); a[20] = f2tf(aR.y); a[40] = f2tf(aR.z); a[60] = f2tf(aR.w);
        }
        float4 aN = aR;
        if (ch < 7) {
            int kb = kh + (ch + 1) * 32;
            aN = *(const float4*)(g_we + (size_t)(r0 + arr) * Dm + kb + akq * 4);
            cpa_wait1();
        } else {
            cpa_wait0();
        }
        barg(g);
        if (ch < 6) {
            int kb = kh + (ch + 2) * 32;
            unsigned wd = wbu[(ch + 2) % 3];
            cpa16(wd + wo0, slab + (size_t)(kb + wk0) * 32 + wsg0 * 4);
            cpa16(wd + wo1, slab + (size_t)(kb + wk1) * 32 + wsg1 * 4);
            cpa_commit();
        }
        const unsigned* Wb = (const unsigned*)wb[ch % 3];
        const int kl = s * 8;
        unsigned a0 = Ag[(kl + (lane & 3)) * 20 + (lane >> 2)];
        unsigned a1 = Ag[(kl + (lane & 3)) * 20 + (lane >> 2) + 8];
        unsigned a2 = Ag[(kl + 4 + (lane & 3)) * 20 + (lane >> 2)];
        unsigned a3 = Ag[(kl + 4 + (lane & 3)) * 20 + (lane >> 2) + 8];
#pragma unroll
        for (int nt = 0; nt < 4; nt++) {
            unsigned b0 = Wb[(kl + (lane & 3)) * 36 + nt * 8 + (lane >> 2)];
            unsigned b1 = Wb[(kl + 4 + (lane & 3)) * 36 + nt * 8 + (lane >> 2)];
            mma_tf32(dacc[nt], a0, a1, a2, a3, b0, b1);
        }
        aR = aN;
    }
    barg(g);
    const int sid = g * 4 + s;
    {
        const int row = lane >> 2, colb = (lane & 3) * 2;
        float* pb = part + sid * 576;
#pragma unroll
        for (int nt = 0; nt < 4; nt++) {
            pb[row * 36 + nt * 8 + colb]           = dacc[nt][0];
            pb[row * 36 + nt * 8 + colb + 1]       = dacc[nt][1];
            pb[(row + 8) * 36 + nt * 8 + colb]     = dacc[nt][2];
            pb[(row + 8) * 36 + nt * 8 + colb + 1] = dacc[nt][3];
        }
    }
    __syncthreads();
    {
        const int rr = tid >> 5, cc = tid & 31;
        float ve = 0.f, va = 0.f;
#pragma unroll
        for (int p = 0; p < 8; p++)  ve += part[p * 576 + rr * 36 + cc];
#pragma unroll
        for (int p = 8; p < 16; p++) va += part[p * 576 + rr * 36 + cc];
        ve = sigm(ve + be[c0 + cc]);
        va = tanhf(va + ba[c0 + cc]);
        float racc = 0.f;
#pragma unroll 4
        for (int m = 0; m < 64; m++) {
            float wt = wT[rr * 64 + m], wn = wN[rr * 64 + m];
            float* p = &memS[(rr * 64 + m) * 32 + cc];
            float v = *p;
            v = v * (1.0f - wt * ve) + wt * va;
            *p = v;
            racc = fmaf(wn, v, racc);
        }
        g_read[(size_t)(r0 + rr) * Dm + c0 + cc] = racc;
    }
}

// ---------------- hop-LSTM step: tf32 mma, depth-3/2, 16 chunks, FULL UNROLL --
__device__ void stage_lstm(float* sm, const float* __restrict__ bih,
                           const float* __restrict__ bhh, int t, int r0, int c0)
{
    float* part = sm + OFF_PART;
    int* s16 = (int*)(sm + OFF_I16);
    const int tid = threadIdx.x;
    const int w = tid >> 5, lane = tid & 31;
    const int gate = w >> 2, ks = w & 3;
    const int g = tid >> 7, gt = tid & 127;
    if (tid < 16) s16[tid] = g_src[(r0 + tid) * Tlen + t] + 1;
    __syncthreads();

    const float* slab = g_WTl + ((size_t)((c0 >> 5) * 4 + g) << 15);
    int wk[4], wsg[4]; unsigned wo[4];
#pragma unroll
    for (int h = 0; h < 4; h++) {
        int i = gt * 4 + h;
        wk[h] = i >> 3; wsg[h] = i & 7;
        wo[h] = (unsigned)(wk[h] * 36 + wsg[h] * 4) * 4u;
    }
    unsigned wbu[3];
#pragma unroll
    for (int i = 0; i < 3; i++)
        wbu[i] = (unsigned)__cvta_generic_to_shared(sm + i * 9216 + g * 2304);
    unsigned* aL[2];
    aL[0] = (unsigned*)(sm + 27648);
    aL[1] = aL[0] + 1280;

    const int arow = tid & 15, aseg = tid >> 4;
    const float* aF = g_ft + ((size_t)t * Bsz + r0 + arow) * Dm + aseg * 4;
    const float* aH = g_H + ((size_t)s16[arow] * Bsz + r0 + arow) * Dm + aseg * 4;

    {   // prologue: W0 -> buf0, W1 -> buf1
#pragma unroll
        for (int h = 0; h < 4; h++)
            cpa16(wbu[0] + wo[h], slab + (size_t)wk[h] * 32 + wsg[h] * 4);
        cpa_commit();
#pragma unroll
        for (int h = 0; h < 4; h++)
            cpa16(wbu[1] + wo[h], slab + (size_t)(64 + wk[h]) * 32 + wsg[h] * 4);
        cpa_commit();
    }
    float4 aR = make_float4(0.f, 0.f, 0.f, 0.f);
    if (tid < 256) aR = *(const float4*)aF;

    float dacc[4][4] = {};
#pragma unroll
    for (int ch = 0; ch < 16; ch++) {   // FULL UNROLL: %3 indices constant
        unsigned* aLu = aL[ch & 1];
        if (tid < 256) {
            unsigned* a = aLu + (aseg * 4) * 20 + arow;
            a[0]  = f2tf(aR.x); a[20] = f2tf(aR.y);
            a[40] = f2tf(aR.z); a[60] = f2tf(aR.w);
        }
        float4 aN = aR;
        if (ch < 15) {
            int kb = (ch + 1) * 64;
            if (tid < 256) {
                const float* basep = (kb < Dm) ? aF + kb : aH + (kb - Dm);
                aN = *(const float4*)basep;
            }
            cpa_wait1();
        } else {
            cpa_wait0();
        }
        __syncthreads();
        if (ch < 14) {
            int kb = (ch + 2) * 64;
            unsigned wd = wbu[(ch + 2) % 3];
#pragma unroll
            for (int h = 0; h < 4; h++)
                cpa16(wd + wo[h], slab + (size_t)(kb + wk[h]) * 32 + wsg[h] * 4);
            cpa_commit();
        }
        const unsigned* Wg = (const unsigned*)(sm + (ch % 3) * 9216) + gate * 2304;
#pragma unroll
        for (int kt = 0; kt < 2; kt++) {
            const int kl = ks * 16 + kt * 8;
            unsigned a0 = aLu[(kl + (lane & 3)) * 20 + (lane >> 2)];
            unsigned a1 = aLu[(kl + (lane & 3)) * 20 + (lane >> 2) + 8];
            unsigned a2 = aLu[(kl + 4 + (lane & 3)) * 20 + (lane >> 2)];
            unsigned a3 = aLu[(kl + 4 + (lane & 3)) * 20 + (lane >> 2) + 8];
#pragma unroll
            for (int nt = 0; nt < 4; nt++) {
                unsigned b0 = Wg[(kl + (lane & 3)) * 36 + nt * 8 + (lane >> 2)];
                unsigned b1 = Wg[(kl + 4 + (lane & 3)) * 36 + nt * 8 + (lane >> 2)];
                mma_tf32(dacc[nt], a0, a1, a2, a3, b0, b1);
            }
        }
        aR = aN;
    }
    const int sid = gate * 4 + ks;
    {
        const int row = lane >> 2, colb = (lane & 3) * 2;
#pragma unroll
        for (int nt = 0; nt < 4; nt++) {
            float* pb = part + sid * 576;
            pb[row * 36 + nt * 8 + colb]           = dacc[nt][0];
            pb[row * 36 + nt * 8 + colb + 1]       = dacc[nt][1];
            pb[(row + 8) * 36 + nt * 8 + colb]     = dacc[nt][2];
            pb[(row + 8) * 36 + nt * 8 + colb + 1] = dacc[nt][3];
        }
    }
    __syncthreads();
    {
        const int rr = tid >> 5, cc = tid & 31;
        float gi = 0.f, gf = 0.f, gg = 0.f, go = 0.f;
#pragma unroll
        for (int p = 0; p < 4; p++)   gi += part[p * 576 + rr * 36 + cc];
#pragma unroll
        for (int p = 4; p < 8; p++)   gf += part[p * 576 + rr * 36 + cc];
#pragma unroll
        for (int p = 8; p < 12; p++)  gg += part[p * 576 + rr * 36 + cc];
#pragma unroll
        for (int p = 12; p < 16; p++) go += part[p * 576 + rr * 36 + cc];
        const int b = r0 + rr, col = c0 + cc;
        gi += bih[col] + bhh[col];
        gf += bih[512 + col] + bhh[512 + col];
        gg += bih[1024 + col] + bhh[1024 + col];
        go += bih[1536 + col] + bhh[1536 + col];
        float cin = g_C[((size_t)s16[rr] * Bsz + b) * Dm + col];
        float cn = sigm(gf) * cin + sigm(gi) * tanhf(gg);
        float hn = sigm(go) * tanhf(cn);
        g_C[((size_t)(t + 1) * Bsz + b) * Dm + col] = cn;
        g_H[((size_t)(t + 1) * Bsz + b) * Dm + col] = hn;
    }
}

// ---------------- prediction head --------------------------------------------
__device__ void stage_head(const float* __restrict__ Wp, const float* __restrict__ bp,
                           float* __restrict__ out)
{
    const int wp = threadIdx.x >> 5, lane = threadIdx.x & 31;
    for (int bt = blockIdx.x * 16 + wp; bt < Bsz * Tlen; bt += NBLK * 16) {
        const int b = bt / Tlen, t = bt % Tlen;
        const float* h = &g_H[((size_t)(t + 1) * Bsz + b) * Dm];
        float s = 0.f;
        for (int i = lane; i < Dm; i += 32) s = fmaf(h[i], Wp[i], s);
        for (int o = 16; o; o >>= 1) s += __shfl_xor_sync(0xffffffffu, s, o);
        if (lane == 0) out[bt] = sigm(s + bp[0]);
    }
}

// ---------------- the single persistent kernel -------------------------------
__global__ void __launch_bounds__(NTHR, 1) k_persist(
    const int* __restrict__ q, const int* __restrict__ r,
    const float* __restrict__ Mk, const float* __restrict__ Mv0,
    const float* __restrict__ ktab, const float* __restrict__ xtab,
    const float* __restrict__ We, const float* __restrict__ be,
    const float* __restrict__ Wadd, const float* __restrict__ badd,
    const float* __restrict__ Wa, const float* __restrict__ ba,
    const float* __restrict__ Wf, const float* __restrict__ bf,
    const float* __restrict__ Wih, const float* __restrict__ Whh,
    const float* __restrict__ bih, const float* __restrict__ bhh,
    const float* __restrict__ hx0, const float* __restrict__ cx0,
    const float* __restrict__ Wp, const float* __restrict__ bp,
    float* __restrict__ out)
{
    extern __shared__ float sm[];
    const int grp = blockIdx.x & 7;
    const int grp32 = grp * 32;
    unsigned ls = 0, lsr = 0;
    if (threadIdx.x == 0) { ls = g_sense; lsr = g_gsense[grp32]; }
    const int r0 = grp * 16;
    const int c0 = (blockIdx.x >> 3) * 32;

    stage_wtr(Wf, Wa, We, Wadd, Wih, Whh);
    stage_addr(sm, Mk, ktab, q);                          gsync(ls);
    stage_softmax(sm);                                    gsync(ls);
    stage_init(sm, Mv0, hx0, cx0, r0, c0);                gsync(ls);

    for (int t = 0; t < Tlen; t++) {
        stage_fwe<0>(sm, bf, ktab, q, r, t, r0, c0);      gsync_grp(lsr, grp32);
        stage_fwe<1>(sm, ba, xtab, q, r, t, r0, c0);      gsync_grp(lsr, grp32);
        stage_ea(sm, be, badd, t, r0, c0);                gsync_grp(lsr, grp32);
    }
    for (int t = 0; t < Tlen; t++) {
        stage_lstm(sm, bih, bhh, t, r0, c0);              gsync_grp(lsr, grp32);
    }
    gsync(ls);                                            // head reads all rows
    stage_head(Wp, bp, out);
}

// ----------------------------------------------------------------------------
extern "C" void kernel_launch(void* const* d_in, const int* in_sizes, int n_in,
                              void* d_out, int out_size)
{
    const int*   q    = (const int*)d_in[0];
    const int*   r    = (const int*)d_in[1];
    const float* Mk   = (const float*)d_in[2];
    const float* Mv0  = (const float*)d_in[3];
    const float* ktab = (const float*)d_in[4];
    const float* xtab = (const float*)d_in[5];
    const float* We   = (const float*)d_in[6];
    const float* be   = (const float*)d_in[7];
    const float* Wadd = (const float*)d_in[8];
    const float* badd = (const float*)d_in[9];
    const float* Wa   = (const float*)d_in[10];
    const float* ba   = (const float*)d_in[11];
    const float* Wf   = (const float*)d_in[12];
    const float* bf   = (const float*)d_in[13];
    const float* Wih  = (const float*)d_in[14];
    const float* Whh  = (const float*)d_in[15];
    const float* bih  = (const float*)d_in[16];
    const float* bhh  = (const float*)d_in[17];
    const float* hx0  = (const float*)d_in[18];
    const float* cx0  = (const float*)d_in[19];
    const float* Wp   = (const float*)d_in[20];
    const float* bp   = (const float*)d_in[21];
    float* out = (float*)d_out;

    static bool attr_set = false;
    if (!attr_set) {
        cudaFuncSetAttribute(k_persist, cudaFuncAttributeMaxDynamicSharedMemorySize, SMEM_BYTES);
        attr_set = true;
    }
    k_persist<<<NBLK, NTHR, SMEM_BYTES>>>(q, r, Mk, Mv0, ktab, xtab, We, be, Wadd, badd,
                                          Wa, ba, Wf, bf, Wih, Whh, bih, bhh,
                                          hx0, cx0, Wp, bp, out);
}